// round 12
// baseline (speedup 1.0000x reference)
#include <cuda_runtime.h>
#include <math_constants.h>

#define NQ     4096
#define NKV    32768
#define CDIM   256
#define KNN    100
#define NSPLIT 8
#define RANGE  (NKV / NSPLIT)     // 4096
#define TILE   1024               // scan tile (16KB smem)
#define CAPS   768                // per (query,split) segment capacity
#define QPW    4
#define WPB    4
#define AW     4                  // warps (queries) per block in attn
#define NCMAX  128                // compacted survivor cap in attn select
#define FULLM  0xffffffffu

// ---------------- static scratch ----------------
__device__ uint2 g_buf[(size_t)NQ * NSPLIT * CAPS];  // {d2 bits (>=0), kv idx}
__device__ int   g_cnt[NQ * NSPLIT];
__device__ float g_thr2[NQ * 2];                     // two safe bounds per query
__device__ int   g_topk_unused;                      // (kept: ABI stability)

// ---------------- helpers ----------------
__device__ __forceinline__ int warp_sum_i(int v) {
#pragma unroll
    for (int o = 16; o; o >>= 1) v += __shfl_xor_sync(FULLM, v, o);
    return v;
}
__device__ __forceinline__ float warp_sum_f(float v) {
#pragma unroll
    for (int o = 16; o; o >>= 1) v += __shfl_xor_sync(FULLM, v, o);
    return v;
}
__device__ __forceinline__ float warp_max_f(float v) {
#pragma unroll
    for (int o = 16; o; o >>= 1) v = fmaxf(v, __shfl_xor_sync(FULLM, v, o));
    return v;
}
__device__ __forceinline__ int warp_min_i(int v) {
#pragma unroll
    for (int o = 16; o; o >>= 1) v = min(v, __shfl_xor_sync(FULLM, v, o));
    return v;
}

// sorted-4 ascending insert (7 ops, branchless)
#define INS4(M0, M1, M2, M3, D) do {                       \
    float _t1 = fmaxf(M0, D); M0 = fminf(M0, D);           \
    float _t3 = fmaxf(M1, _t1); M1 = fminf(M1, _t1);       \
    float _t5 = fmaxf(M2, _t3); M2 = fminf(M2, _t3);       \
    M3 = fminf(M3, _t5);                                   \
} while (0)

// ================= kernel 0: per-query safe threshold (2 warps/query) ======
// Warp (q, half) samples kv points [half*4096, half*4096+4096). Per-lane two
// sorted-4 chains -> kth(100) of 256 stash values. Each half's kth >= its
// half-sample's true 100th >= global 100th, so both bounds are SAFE; the
// scan uses min(bound0, bound1) (tighter, still safe). Grid = 8192 warps.
__global__ void __launch_bounds__(128) knn_thr(
    const float* __restrict__ qpos, const float* __restrict__ kpos)
{
    const int lane = threadIdx.x & 31, w = threadIdx.x >> 5;
    const int q = blockIdx.x * 2 + (w >> 1);
    const int half = w & 1;
    const int fbase = half * 3072;         // 4096 points * 3 floats / 4

    const float qx = qpos[3 * q], qy = qpos[3 * q + 1], qz = qpos[3 * q + 2];
    const float c0 = fmaf(qx, qx, fmaf(qy, qy, qz * qz));
    const float ax = -2.f * qx, ay = -2.f * qy, az = -2.f * qz;

    const float4* kp4 = (const float4*)kpos;

    float A0 = CUDART_INF_F, A1 = A0, A2 = A0, A3 = A0;   // chain A
    float B0 = A0, B1 = A0, B2 = A0, B3 = A0;             // chain B

    for (int s = 0; s < 32; s++) {
        const int b = fbase + s * 96 + lane * 3;   // 4 candidates = 3 float4s
        const float4 f0 = __ldg(kp4 + b);
        const float4 f1 = __ldg(kp4 + b + 1);
        const float4 f2 = __ldg(kp4 + b + 2);
        float w0 = fmaf(f0.x, f0.x, fmaf(f0.y, f0.y, f0.z * f0.z));
        float w1 = fmaf(f0.w, f0.w, fmaf(f1.x, f1.x, f1.y * f1.y));
        float w2 = fmaf(f1.z, f1.z, fmaf(f1.w, f1.w, f2.x * f2.x));
        float w3 = fmaf(f2.y, f2.y, fmaf(f2.z, f2.z, f2.w * f2.w));
        float d0 = fmaf(ax, f0.x, w0); d0 = fmaf(ay, f0.y, d0); d0 = fmaf(az, f0.z, d0); d0 += c0;
        float d1 = fmaf(ax, f0.w, w1); d1 = fmaf(ay, f1.x, d1); d1 = fmaf(az, f1.y, d1); d1 += c0;
        float d2 = fmaf(ax, f1.z, w2); d2 = fmaf(ay, f1.w, d2); d2 = fmaf(az, f2.x, d2); d2 += c0;
        float d3 = fmaf(ax, f2.y, w3); d3 = fmaf(ay, f2.z, d3); d3 = fmaf(az, f2.w, d3); d3 += c0;
        INS4(A0, A1, A2, A3, d0);
        INS4(B0, B1, B2, B3, d1);
        INS4(A0, A1, A2, A3, d2);
        INS4(B0, B1, B2, B3, d3);
    }
    A0 = fmaxf(A0, 0.f); A1 = fmaxf(A1, 0.f); A2 = fmaxf(A2, 0.f); A3 = fmaxf(A3, 0.f);
    B0 = fmaxf(B0, 0.f); B1 = fmaxf(B1, 0.f); B2 = fmaxf(B2, 0.f); B3 = fmaxf(B3, 0.f);

    unsigned lo = 0u, hi = 0x7f800000u;
#pragma unroll
    for (int it = 0; it < 24; it++) {
        unsigned mid = lo + ((hi - lo) >> 1);
        int c = (__float_as_uint(A0) <= mid) + (__float_as_uint(A1) <= mid)
              + (__float_as_uint(A2) <= mid) + (__float_as_uint(A3) <= mid)
              + (__float_as_uint(B0) <= mid) + (__float_as_uint(B1) <= mid)
              + (__float_as_uint(B2) <= mid) + (__float_as_uint(B3) <= mid);
        c = warp_sum_i(c);
        if (c >= KNN) hi = mid; else lo = mid + 1u;
    }
    if (lane == 0) g_thr2[q * 2 + half] = __uint_as_float(hi);
}

// ================= kernel 1: candidate scan (KV-split x8) =================
// Hot loop: 3 FMA + compare; ballot result is warp-uniform so `if (m)` skips
// the append bookkeeping entirely on empty steps.
__global__ void __launch_bounds__(32 * WPB, 8) knn_scan(
    const float* __restrict__ qpos, const float* __restrict__ kpos)
{
    __shared__ float4 s_tile[TILE];

    const int tid = threadIdx.x, lane = tid & 31, warp = tid >> 5;
    const int qbase = blockIdx.x * (WPB * QPW) + warp * QPW;
    const int split = blockIdx.y;
    const int kbase = split * RANGE;
    const unsigned lt = (1u << lane) - 1u;

    float ax[QPW], ay[QPW], az[QPW], c0[QPW], tj[QPW];
    int cnt[QPW];
#pragma unroll
    for (int j = 0; j < QPW; j++) {
        int q = qbase + j;
        float qx = qpos[3 * q], qy = qpos[3 * q + 1], qz = qpos[3 * q + 2];
        c0[j] = fmaf(qx, qx, fmaf(qy, qy, qz * qz));
        ax[j] = -2.f * qx; ay[j] = -2.f * qy; az[j] = -2.f * qz;
        // min of the two safe bounds; bump covers FMA-order rounding diffs
        float th = fminf(g_thr2[q * 2], g_thr2[q * 2 + 1]);
        tj[j] = th * 1.000004f - c0[j];
        cnt[j] = 0;
    }

    uint2* seg[QPW];
#pragma unroll
    for (int j = 0; j < QPW; j++)
        seg[j] = g_buf + ((size_t)(qbase + j) * NSPLIT + split) * CAPS;

    for (int t0 = 0; t0 < RANGE; t0 += TILE) {
        __syncthreads();
        for (int i = tid; i < TILE; i += 32 * WPB) {
            int g = kbase + t0 + i;
            float x = kpos[3 * g], y = kpos[3 * g + 1], z = kpos[3 * g + 2];
            s_tile[i] = make_float4(x, y, z, fmaf(x, x, fmaf(y, y, z * z)));
        }
        __syncthreads();
#pragma unroll 2
        for (int i = lane; i < TILE; i += 32) {
            float4 kp = s_tile[i];
#pragma unroll
            for (int j = 0; j < QPW; j++) {
                float dd = fmaf(ax[j], kp.x, kp.w);
                dd = fmaf(ay[j], kp.y, dd);
                dd = fmaf(az[j], kp.z, dd);
                bool p = (dd <= tj[j]);
                unsigned m = __ballot_sync(FULLM, p);
                if (m) {                       // warp-uniform branch
                    int pos = cnt[j] + __popc(m & lt);
                    if (p && pos < CAPS)
                        seg[j][pos] = make_uint2(__float_as_uint(fmaxf(dd + c0[j], 0.f)),
                                                 (unsigned)(kbase + t0 + i));
                    cnt[j] += __popc(m);
                }
            }
        }
    }
    if (lane == 0) {
#pragma unroll
        for (int j = 0; j < QPW; j++)
            g_cnt[(qbase + j) * NSPLIT + split] = min(cnt[j], CAPS);
    }
}

// ================= kernel 2: fused select + attention + LN, warp/query =====
__global__ void __launch_bounds__(32 * AW) attn_ln(
    const float* __restrict__ qf, const float* __restrict__ kf,
    const float* __restrict__ vf, const float* __restrict__ gamma,
    const float* __restrict__ beta, float* __restrict__ out)
{
    __shared__ int   s_idx[AW][100];
    __shared__ float s_p[AW][104];
    __shared__ int   s_hist[AW][257];
    __shared__ uint2 s_cand[AW][NCMAX];
    __shared__ int   s_tie[AW][64];

    const int lane = threadIdx.x & 31, w = threadIdx.x >> 5;
    const int q = blockIdx.x * AW + w;
    const unsigned lt = (1u << lane) - 1u;

    // ---------- exact top-100 select (per warp) ----------
    {
        const uint2* seg[NSPLIT];
        int c[NSPLIT];
#pragma unroll
        for (int s = 0; s < NSPLIT; s++) {
            seg[s] = g_buf + ((size_t)q * NSPLIT + s) * CAPS;
            c[s] = g_cnt[q * NSPLIT + s];
        }

        // -- rounds 1-2: 8-bit histograms over gmem (top 16 bits of 100th) --
        unsigned prefix = 0;
        int kk = KNN;
#pragma unroll
        for (int shift = 24; shift >= 16; shift -= 8) {
            for (int b = lane; b < 256; b += 32) s_hist[w][b] = 0;
            __syncwarp();
            const unsigned himask = (shift == 24) ? 0u : 0xff000000u;
#pragma unroll
            for (int s = 0; s < NSPLIT; s++) {
                for (int base = 0; base < c[s]; base += 32) {
                    int i = base + lane;
                    bool valid = (i < c[s]);
                    unsigned bits = valid ? seg[s][i].x : 0u;
                    valid = valid && ((bits & himask) == prefix);
                    unsigned act = __ballot_sync(FULLM, valid);
                    if (valid) {
                        int bin = (bits >> shift) & 0xFF;
                        unsigned peers = __match_any_sync(act, bin);
                        if ((int)__ffs(peers) - 1 == lane)
                            atomicAdd(&s_hist[w][bin], __popc(peers));
                    }
                }
            }
            __syncwarp();
            int loc[8], sum = 0;
#pragma unroll
            for (int t = 0; t < 8; t++) { loc[t] = sum; sum += s_hist[w][lane * 8 + t]; }
            int ex = sum;
#pragma unroll
            for (int o = 1; o < 32; o <<= 1) {
                int tv = __shfl_up_sync(FULLM, ex, o);
                if (lane >= o) ex += tv;
            }
            ex -= sum;
            int found = 999, cbf = 0;
#pragma unroll
            for (int t = 0; t < 8; t++) {
                int cb = ex + loc[t], ct = s_hist[w][lane * 8 + t];
                if (found == 999 && kk > cb && kk <= cb + ct) { found = lane * 8 + t; cbf = cb; }
            }
            int mf = warp_min_i(found);
            unsigned who = __ballot_sync(FULLM, found == mf);
            cbf = __shfl_sync(FULLM, cbf, __ffs(who) - 1);
            prefix |= ((unsigned)mf) << shift;
            kk -= cbf;
            __syncwarp();
        }

        // -- combined pass: emit all < prefix block; compact top16==prefix --
        int nout = 0, ncand = 0;
#pragma unroll
        for (int s = 0; s < NSPLIT; s++) {
            for (int base = 0; base < c[s]; base += 32) {
                int i = base + lane;
                bool valid = (i < c[s]);
                uint2 e = valid ? seg[s][i] : make_uint2(0xffffffffu, 0u);
                bool w1 = (e.x < prefix);
                unsigned m1 = __ballot_sync(FULLM, w1);
                if (m1) {
                    if (w1) s_idx[w][nout + __popc(m1 & lt)] = (int)e.y;
                    nout += __popc(m1);
                }
                bool h = ((e.x & 0xffff0000u) == prefix);
                unsigned mh = __ballot_sync(FULLM, h);
                if (mh) {
                    int pos = ncand + __popc(mh & lt);
                    if (h && pos < NCMAX) s_cand[w][pos] = e;
                    ncand += __popc(mh);
                }
            }
        }
        __syncwarp();

        if (ncand <= NCMAX) {
            // -- low-16 bits of the 100th: warp binary search over smem --
            unsigned b0 = (lane < ncand)      ? (s_cand[w][lane].x & 0xffffu)      : 0xffffffffu;
            unsigned b1 = (lane + 32 < ncand) ? (s_cand[w][lane + 32].x & 0xffffu) : 0xffffffffu;
            unsigned b2 = (lane + 64 < ncand) ? (s_cand[w][lane + 64].x & 0xffffu) : 0xffffffffu;
            unsigned b3 = (lane + 96 < ncand) ? (s_cand[w][lane + 96].x & 0xffffu) : 0xffffffffu;
            unsigned lo = 0u, hi = 0xffffu;
#pragma unroll
            for (int it = 0; it < 16; it++) {
                unsigned mid = lo + ((hi - lo) >> 1);
                int cc = (b0 <= mid) + (b1 <= mid) + (b2 <= mid) + (b3 <= mid);
                cc = warp_sum_i(cc);
                if (cc >= kk) hi = mid; else lo = mid + 1u;
            }
            // -- emit survivors with low16 < lo --
            for (int base = 0; base < ncand; base += 32) {
                int i = base + lane;
                bool v = (i < ncand) && ((s_cand[w][i].x & 0xffffu) < lo);
                unsigned m1 = __ballot_sync(FULLM, v);
                if (m1) {
                    if (v) s_idx[w][nout + __popc(m1 & lt)] = (int)s_cand[w][i].y;
                    nout += __popc(m1);
                }
            }
            // -- ties (low16 == lo): smallest kv indices win --
            int ntie = 0;
            for (int base = 0; base < ncand; base += 32) {
                int i = base + lane;
                bool v = (i < ncand) && ((s_cand[w][i].x & 0xffffu) == lo);
                unsigned m2 = __ballot_sync(FULLM, v);
                if (v) {
                    int p = ntie + __popc(m2 & lt);
                    if (p < 64) s_tie[w][p] = (int)s_cand[w][i].y;
                }
                ntie += __popc(m2);
            }
            __syncwarp();
            const int tc = min(ntie, 64);
            const int need = KNN - nout;
            for (int r = 0; r < need; r++) {
                int v0 = (lane < tc) ? s_tie[w][lane] : 0x7fffffff;
                int v1 = (lane + 32 < tc) ? s_tie[w][lane + 32] : 0x7fffffff;
                int mv = warp_min_i(min(v0, v1));
                if (v0 == mv && lane < tc) s_tie[w][lane] = 0x7fffffff;
                else if (v1 == mv && lane + 32 < tc) s_tie[w][lane + 32] = 0x7fffffff;
                if (lane == 0) s_idx[w][nout + r] = mv;
                __syncwarp();
            }
        } else {
            // -- fallback (essentially never): full gmem resolution --
            unsigned lo = 0u, hi = 0xffffu;
            while (lo < hi) {
                unsigned mid = lo + ((hi - lo) >> 1);
                int cc = 0;
#pragma unroll
                for (int s = 0; s < NSPLIT; s++)
                    for (int base = 0; base < c[s]; base += 32) {
                        int i = base + lane;
                        if (i < c[s]) {
                            unsigned bits = seg[s][i].x;
                            cc += ((bits & 0xffff0000u) == prefix && (bits & 0xffffu) <= mid);
                        }
                    }
                cc = warp_sum_i(cc);
                if (cc >= kk) hi = mid; else lo = mid + 1u;
            }
            const unsigned Tb = prefix | lo;
            nout = 0;
#pragma unroll
            for (int s = 0; s < NSPLIT; s++) {
                for (int base = 0; base < c[s]; base += 32) {
                    int i = base + lane;
                    bool valid = (i < c[s]);
                    uint2 e = valid ? seg[s][i] : make_uint2(0xffffffffu, 0u);
                    bool w1 = (e.x < Tb);
                    unsigned m1 = __ballot_sync(FULLM, w1);
                    if (w1) s_idx[w][nout + __popc(m1 & lt)] = (int)e.y;
                    nout += __popc(m1);
                }
            }
            int ntie = 0;
#pragma unroll
            for (int s = 0; s < NSPLIT; s++)
                for (int base = 0; base < c[s]; base += 32) {
                    int i = base + lane;
                    bool v = (i < c[s]) && (seg[s][i].x == Tb);
                    unsigned m2 = __ballot_sync(FULLM, v);
                    if (v) {
                        int p = ntie + __popc(m2 & lt);
                        if (p < 64) s_tie[w][p] = (int)seg[s][i].y;
                    }
                    ntie += __popc(m2);
                }
            __syncwarp();
            const int tc = min(ntie, 64);
            const int need = KNN - nout;
            for (int r = 0; r < need; r++) {
                int v0 = (lane < tc) ? s_tie[w][lane] : 0x7fffffff;
                int v1 = (lane + 32 < tc) ? s_tie[w][lane + 32] : 0x7fffffff;
                int mv = warp_min_i(min(v0, v1));
                if (v0 == mv && lane < tc) s_tie[w][lane] = 0x7fffffff;
                else if (v1 == mv && lane + 32 < tc) s_tie[w][lane + 32] = 0x7fffffff;
                if (lane == 0) s_idx[w][nout + r] = mv;
                __syncwarp();
            }
        }
    }
    __syncwarp();

    // ---------- attention ----------
    const float4* qf4 = (const float4*)(qf + (size_t)q * CDIM);
    const float4 qa = qf4[lane], qb = qf4[32 + lane];

    // QK^T: 25 groups of 4 rows (8 LDG.128 in flight)
    for (int gr = 0; gr < 25; gr++) {
        const int4 id = *(const int4*)&s_idx[w][gr * 4];
        const float4* k0 = (const float4*)(kf + (size_t)id.x * CDIM);
        const float4* k1 = (const float4*)(kf + (size_t)id.y * CDIM);
        const float4* k2 = (const float4*)(kf + (size_t)id.z * CDIM);
        const float4* k3 = (const float4*)(kf + (size_t)id.w * CDIM);
        float4 a0 = k0[lane], b0 = k0[32 + lane];
        float4 a1 = k1[lane], b1 = k1[32 + lane];
        float4 a2 = k2[lane], b2 = k2[32 + lane];
        float4 a3 = k3[lane], b3 = k3[32 + lane];
        float s0 = qa.x * a0.x, s1 = qa.x * a1.x, s2 = qa.x * a2.x, s3 = qa.x * a3.x;
        s0 = fmaf(qa.y, a0.y, s0); s1 = fmaf(qa.y, a1.y, s1); s2 = fmaf(qa.y, a2.y, s2); s3 = fmaf(qa.y, a3.y, s3);
        s0 = fmaf(qa.z, a0.z, s0); s1 = fmaf(qa.z, a1.z, s1); s2 = fmaf(qa.z, a2.z, s2); s3 = fmaf(qa.z, a3.z, s3);
        s0 = fmaf(qa.w, a0.w, s0); s1 = fmaf(qa.w, a1.w, s1); s2 = fmaf(qa.w, a2.w, s2); s3 = fmaf(qa.w, a3.w, s3);
        s0 = fmaf(qb.x, b0.x, s0); s1 = fmaf(qb.x, b1.x, s1); s2 = fmaf(qb.x, b2.x, s2); s3 = fmaf(qb.x, b3.x, s3);
        s0 = fmaf(qb.y, b0.y, s0); s1 = fmaf(qb.y, b1.y, s1); s2 = fmaf(qb.y, b2.y, s2); s3 = fmaf(qb.y, b3.y, s3);
        s0 = fmaf(qb.z, b0.z, s0); s1 = fmaf(qb.z, b1.z, s1); s2 = fmaf(qb.z, b2.z, s2); s3 = fmaf(qb.z, b3.z, s3);
        s0 = fmaf(qb.w, b0.w, s0); s1 = fmaf(qb.w, b1.w, s1); s2 = fmaf(qb.w, b2.w, s2); s3 = fmaf(qb.w, b3.w, s3);
#pragma unroll
        for (int o = 16; o; o >>= 1) {
            s0 += __shfl_xor_sync(FULLM, s0, o);
            s1 += __shfl_xor_sync(FULLM, s1, o);
            s2 += __shfl_xor_sync(FULLM, s2, o);
            s3 += __shfl_xor_sync(FULLM, s3, o);
        }
        if (lane == 0)
            *(float4*)&s_p[w][gr * 4] =
                make_float4(s0 * 0.0625f, s1 * 0.0625f, s2 * 0.0625f, s3 * 0.0625f);
    }
    __syncwarp();

    // softmax within the warp
    float l0 = s_p[w][lane], l1 = s_p[w][lane + 32], l2 = s_p[w][lane + 64];
    float l3 = (lane < 4) ? s_p[w][lane + 96] : -CUDART_INF_F;
    float mx = warp_max_f(fmaxf(fmaxf(l0, l1), fmaxf(l2, l3)));
    float e0 = __expf(l0 - mx), e1 = __expf(l1 - mx), e2 = __expf(l2 - mx);
    float e3 = (lane < 4) ? __expf(l3 - mx) : 0.f;
    float sm = warp_sum_f((e0 + e1) + (e2 + e3));
    s_p[w][lane] = e0; s_p[w][lane + 32] = e1; s_p[w][lane + 64] = e2;
    if (lane < 4) s_p[w][lane + 96] = e3;
    const float sc = 2.f / sm;   // res fully overwritten by x: y = 2x; fold 1/sum
    __syncwarp();

    // PV: 2 chains x 4 rows per group
    float4 A0 = make_float4(0.f, 0.f, 0.f, 0.f), B0 = A0, A1 = A0, B1 = A0;
    for (int gr = 0; gr < 25; gr++) {
        const int4 id = *(const int4*)&s_idx[w][gr * 4];
        const float4 p4 = *(const float4*)&s_p[w][gr * 4];
        const float4* v0 = (const float4*)(vf + (size_t)id.x * CDIM);
        const float4* v1 = (const float4*)(vf + (size_t)id.y * CDIM);
        const float4* v2 = (const float4*)(vf + (size_t)id.z * CDIM);
        const float4* v3 = (const float4*)(vf + (size_t)id.w * CDIM);
        float4 va0 = v0[lane], vb0 = v0[32 + lane];
        float4 va1 = v1[lane], vb1 = v1[32 + lane];
        float4 va2 = v2[lane], vb2 = v2[32 + lane];
        float4 va3 = v3[lane], vb3 = v3[32 + lane];
        A0.x = fmaf(p4.x, va0.x, A0.x); A0.y = fmaf(p4.x, va0.y, A0.y);
        A0.z = fmaf(p4.x, va0.z, A0.z); A0.w = fmaf(p4.x, va0.w, A0.w);
        B0.x = fmaf(p4.x, vb0.x, B0.x); B0.y = fmaf(p4.x, vb0.y, B0.y);
        B0.z = fmaf(p4.x, vb0.z, B0.z); B0.w = fmaf(p4.x, vb0.w, B0.w);
        A1.x = fmaf(p4.y, va1.x, A1.x); A1.y = fmaf(p4.y, va1.y, A1.y);
        A1.z = fmaf(p4.y, va1.z, A1.z); A1.w = fmaf(p4.y, va1.w, A1.w);
        B1.x = fmaf(p4.y, vb1.x, B1.x); B1.y = fmaf(p4.y, vb1.y, B1.y);
        B1.z = fmaf(p4.y, vb1.z, B1.z); B1.w = fmaf(p4.y, vb1.w, B1.w);
        A0.x = fmaf(p4.z, va2.x, A0.x); A0.y = fmaf(p4.z, va2.y, A0.y);
        A0.z = fmaf(p4.z, va2.z, A0.z); A0.w = fmaf(p4.z, va2.w, A0.w);
        B0.x = fmaf(p4.z, vb2.x, B0.x); B0.y = fmaf(p4.z, vb2.y, B0.y);
        B0.z = fmaf(p4.z, vb2.z, B0.z); B0.w = fmaf(p4.z, vb2.w, B0.w);
        A1.x = fmaf(p4.w, va3.x, A1.x); A1.y = fmaf(p4.w, va3.y, A1.y);
        A1.z = fmaf(p4.w, va3.z, A1.z); A1.w = fmaf(p4.w, va3.w, A1.w);
        B1.x = fmaf(p4.w, vb3.x, B1.x); B1.y = fmaf(p4.w, vb3.y, B1.y);
        B1.z = fmaf(p4.w, vb3.z, B1.z); B1.w = fmaf(p4.w, vb3.w, B1.w);
    }
    float4 A = make_float4((A0.x + A1.x) * sc, (A0.y + A1.y) * sc,
                           (A0.z + A1.z) * sc, (A0.w + A1.w) * sc);
    float4 B = make_float4((B0.x + B1.x) * sc, (B0.y + B1.y) * sc,
                           (B0.z + B1.z) * sc, (B0.w + B1.w) * sc);

    // LayerNorm within the warp
    float s = ((A.x + A.y) + (A.z + A.w)) + ((B.x + B.y) + (B.z + B.w));
    const float mean = warp_sum_f(s) * (1.f / CDIM);
    float dAx = A.x - mean, dAy = A.y - mean, dAz = A.z - mean, dAw = A.w - mean;
    float dBx = B.x - mean, dBy = B.y - mean, dBz = B.z - mean, dBw = B.w - mean;
    float s2 = ((dAx * dAx + dAy * dAy) + (dAz * dAz + dAw * dAw))
             + ((dBx * dBx + dBy * dBy) + (dBz * dBz + dBw * dBw));
    const float rstd = rsqrtf(warp_sum_f(s2) * (1.f / CDIM) + 1e-5f);

    const float4* g4 = (const float4*)gamma;
    const float4* b4 = (const float4*)beta;
    float4 ga = g4[lane], gb = g4[32 + lane];
    float4 ba = b4[lane], bb = b4[32 + lane];
    float4* o4 = (float4*)(out + (size_t)q * CDIM);
    o4[lane] = make_float4(fmaf(dAx * rstd, ga.x, ba.x),
                           fmaf(dAy * rstd, ga.y, ba.y),
                           fmaf(dAz * rstd, ga.z, ba.z),
                           fmaf(dAw * rstd, ga.w, ba.w));
    o4[32 + lane] = make_float4(fmaf(dBx * rstd, gb.x, bb.x),
                                fmaf(dBy * rstd, gb.y, bb.y),
                                fmaf(dBz * rstd, gb.z, bb.z),
                                fmaf(dBw * rstd, gb.w, bb.w));
}

// ---------------- launch ----------------
extern "C" void kernel_launch(void* const* d_in, const int* in_sizes, int n_in,
                              void* d_out, int out_size) {
    (void)in_sizes; (void)n_in; (void)out_size;
    const float* qf    = (const float*)d_in[1];
    const float* kf    = (const float*)d_in[2];
    const float* vf    = (const float*)d_in[3];
    const float* qpos  = (const float*)d_in[4];
    const float* kpos  = (const float*)d_in[5];
    const float* gamma = (const float*)d_in[6];
    const float* beta  = (const float*)d_in[7];

    knn_thr<<<NQ / 2, 128>>>(qpos, kpos);
    knn_scan<<<dim3(NQ / (WPB * QPW), NSPLIT), 32 * WPB>>>(qpos, kpos);
    attn_ln<<<NQ / AW, 32 * AW>>>(qf, kf, vf, gamma, beta, (float*)d_out);
}